// round 2
// baseline (speedup 1.0000x reference)
#include <cuda_runtime.h>
#include <cstdint>

#define BB 256
#define TT 512
#define IND 64
#define HH 512
#define GG 2048   // 4*H
#define NCTA 128

// ---------------- device scratch (no allocations allowed) ----------------
__device__ float g_xproj[(size_t)TT * BB * GG];  // 1 GiB: x-projection for current layer
__device__ float g_hseq [(size_t)TT * BB * HH];  // layer-0 hidden sequence
__device__ float g_hbuf [2][BB * HH];            // double-buffered h
__device__ float g_Whh  [2][GG * HH];            // permuted + tf32-rounded
__device__ float g_Wih0 [GG * IND];
__device__ float g_Wih1 [GG * HH];
__device__ float g_bias [2][GG];                 // b_ih + b_hh, permuted
__device__ unsigned g_bar_count = 0;
__device__ unsigned g_bar_gen   = 0;

// ---------------- helpers ----------------
__device__ __forceinline__ float tf32f(float x) {
    uint32_t u;
    asm("cvt.rna.tf32.f32 %0, %1;" : "=r"(u) : "f"(x));
    return __uint_as_float(u);
}

__device__ __forceinline__ void mma_tf32(float& c0, float& c1, float& c2, float& c3,
                                         uint32_t a0, uint32_t a1, uint32_t a2, uint32_t a3,
                                         uint32_t b0, uint32_t b1) {
    asm volatile(
        "mma.sync.aligned.m16n8k8.row.col.f32.tf32.tf32.f32 "
        "{%0,%1,%2,%3}, {%4,%5,%6,%7}, {%8,%9}, {%0,%1,%2,%3};\n"
        : "+f"(c0), "+f"(c1), "+f"(c2), "+f"(c3)
        : "r"(a0), "r"(a1), "r"(a2), "r"(a3), "r"(b0), "r"(b1));
}

__device__ __forceinline__ float sigmf(float x) { return 1.0f / (1.0f + expf(-x)); }

__device__ __forceinline__ void cpasync16(uint32_t saddr, const void* g) {
    asm volatile("cp.async.cg.shared.global [%0], [%1], 16;\n" :: "r"(saddr), "l"(g));
}
__device__ __forceinline__ void cpasync_commit() {
    asm volatile("cp.async.commit_group;\n");
}
__device__ __forceinline__ void cpasync_waitall() {
    asm volatile("cp.async.wait_all;\n" ::: "memory");
}

// software grid barrier: all NCTA CTAs guaranteed co-resident (1 per SM)
__device__ __forceinline__ void grid_sync() {
    __syncthreads();
    if (threadIdx.x == 0) {
        __threadfence();
        unsigned gen = atomicAdd(&g_bar_gen, 0u);
        unsigned a = atomicAdd(&g_bar_count, 1u);
        if (a == NCTA - 1u) {
            atomicExch(&g_bar_count, 0u);
            __threadfence();
            atomicAdd(&g_bar_gen, 1u);
        } else {
            while (atomicAdd(&g_bar_gen, 0u) == gen) __nanosleep(64);
        }
        __threadfence();
    }
    __syncthreads();
}

// ---------------- weight permute + tf32 pre-round ----------------
// new row index g' = j*4 + gate  <-  old row = gate*H + j
__global__ void prep_kernel(const float* __restrict__ Wih0, const float* __restrict__ Whh0,
                            const float* __restrict__ bih0, const float* __restrict__ bhh0,
                            const float* __restrict__ Wih1, const float* __restrict__ Whh1,
                            const float* __restrict__ bih1, const float* __restrict__ bhh1) {
    int stride = gridDim.x * blockDim.x;
    int tid = blockIdx.x * blockDim.x + threadIdx.x;
    for (int i = tid; i < GG * HH; i += stride) {
        int orow = i / HH, k = i - orow * HH;
        int j = orow >> 2, gate = orow & 3;
        int src = (gate * HH + j) * HH + k;
        g_Whh[0][i] = tf32f(Whh0[src]);
        g_Whh[1][i] = tf32f(Whh1[src]);
        g_Wih1[i]   = tf32f(Wih1[src]);
    }
    for (int i = tid; i < GG * IND; i += stride) {
        int orow = i / IND, k = i - orow * IND;
        int j = orow >> 2, gate = orow & 3;
        g_Wih0[i] = tf32f(Wih0[(gate * HH + j) * IND + k]);
    }
    for (int i = tid; i < GG; i += stride) {
        int j = i >> 2, gate = i & 3;
        int src = gate * HH + j;
        g_bias[0][i] = bih0[src] + bhh0[src];
        g_bias[1][i] = bih1[src] + bhh1[src];
    }
}

// ---------------- input projection GEMM ----------------
#define KC 64
template <int K, int LAYER>
__global__ void __launch_bounds__(256)
inproj_kernel(const float* __restrict__ Ain) {
    __shared__ float sA[64][KC + 4];
    __shared__ float sB[64][KC + 4];

    const float* __restrict__ W    = (LAYER == 0) ? g_Wih0 : g_Wih1;
    const float* __restrict__ bias = g_bias[LAYER];
    const float* __restrict__ A    = (LAYER == 0) ? Ain : g_hseq;
    const long strideT = (LAYER == 0) ? (long)IND : (long)BB * HH;
    const long strideB = (LAYER == 0) ? (long)TT * IND : (long)HH;

    int tid = threadIdx.x;
    int m0 = blockIdx.x * 64;
    int n0 = blockIdx.y * 64;
    int t  = m0 >> 8;
    int b0 = m0 & 255;
    const float* Abase = A + t * strideT + b0 * strideB;

    int w = tid >> 5, lane = tid & 31, q = lane & 3, gq = lane >> 2;
    int wm = w & 3, wn = w >> 2;

    float acc[4][4] = {};

    for (int kc = 0; kc < K; kc += KC) {
#pragma unroll
        for (int r = 0; r < 4; r++) {
            int idx = tid + r * 256;
            int row = idx >> 4;
            int c4  = idx & 15;
            float4 v = *reinterpret_cast<const float4*>(Abase + row * strideB + kc + c4 * 4);
            v.x = tf32f(v.x); v.y = tf32f(v.y); v.z = tf32f(v.z); v.w = tf32f(v.w);
            *reinterpret_cast<float4*>(&sA[row][c4 * 4]) = v;
            float4 wv = *reinterpret_cast<const float4*>(W + (long)(n0 + row) * K + kc + c4 * 4);
            *reinterpret_cast<float4*>(&sB[row][c4 * 4]) = wv;
        }
        __syncthreads();
#pragma unroll
        for (int ks = 0; ks < KC / 8; ks++) {
            int k0 = ks * 8;
            uint32_t a0 = __float_as_uint(sA[wm * 16 + gq    ][k0 + q]);
            uint32_t a1 = __float_as_uint(sA[wm * 16 + gq + 8][k0 + q]);
            uint32_t a2 = __float_as_uint(sA[wm * 16 + gq    ][k0 + q + 4]);
            uint32_t a3 = __float_as_uint(sA[wm * 16 + gq + 8][k0 + q + 4]);
#pragma unroll
            for (int nt = 0; nt < 4; nt++) {
                int n = wn * 32 + nt * 8 + gq;
                uint32_t b0f = __float_as_uint(sB[n][k0 + q]);
                uint32_t b1f = __float_as_uint(sB[n][k0 + q + 4]);
                mma_tf32(acc[nt][0], acc[nt][1], acc[nt][2], acc[nt][3],
                         a0, a1, a2, a3, b0f, b1f);
            }
        }
        __syncthreads();
    }

#pragma unroll
    for (int nt = 0; nt < 4; nt++) {
        int col = n0 + wn * 32 + nt * 8 + q * 2;
        float bv0 = bias[col], bv1 = bias[col + 1];
        int row = m0 + wm * 16 + gq;
        *reinterpret_cast<float2*>(g_xproj + (size_t)row * GG + col) =
            make_float2(acc[nt][0] + bv0, acc[nt][1] + bv1);
        *reinterpret_cast<float2*>(g_xproj + (size_t)(row + 8) * GG + col) =
            make_float2(acc[nt][2] + bv0, acc[nt][3] + bv1);
    }
}

// ---------------- persistent LSTM scan (all 512 timesteps in one launch) ----------------
// smem: sW [64][516] (CTA's Whh slice, resident), sA double buffer [2][64][68]
#define WPAD 516
#define APAD 68
#define SW_FLOATS (64 * WPAD)
#define SA_FLOATS (64 * APAD)
#define SMEM_SCAN ((SW_FLOATS + 2 * SA_FLOATS) * 4)

template <int LAYER>
__global__ void __launch_bounds__(256, 1)
scan_kernel() {
    extern __shared__ float smem[];
    float* sW  = smem;
    float* sA0 = smem + SW_FLOATS;
    float* sA1 = sA0 + SA_FLOATS;
    uint32_t sA0u = (uint32_t)__cvta_generic_to_shared(sA0);
    uint32_t sA1u = (uint32_t)__cvta_generic_to_shared(sA1);

    const float* __restrict__ Whh = g_Whh[LAYER];

    int tid = threadIdx.x;
    int bi = blockIdx.x & 3;       // batch tile
    int ni = blockIdx.x >> 2;      // gate-column tile
    int b0 = bi * 64;
    int n0 = ni * 64;
    int j0 = ni * 16;

    int w = tid >> 5, lane = tid & 31, q = lane & 3, gq = lane >> 2;
    int wm = w & 3, wn = w >> 2;

    // ---- load resident W slice: rows n0..n0+63, K = 512 ----
    for (int i = tid; i < 64 * 128; i += 256) {          // float4 granules
        int row = i >> 7, c4 = i & 127;
        float4 wv = *reinterpret_cast<const float4*>(Whh + (long)(n0 + row) * HH + c4 * 4);
        *reinterpret_cast<float4*>(&sW[row * WPAD + c4 * 4]) = wv;
    }

    // ---- zero my slice of h0 and register-resident c ----
    float c_reg[4];
#pragma unroll
    for (int s = 0; s < 4; s++) {
        c_reg[s] = 0.0f;
        int idx = tid + s * 256;
        int b = idx >> 4, j = idx & 15;
        g_hbuf[0][(b0 + b) * HH + j0 + j] = 0.0f;
    }
    grid_sync();

    for (int t = 0; t < TT; t++) {
        const float* __restrict__ hprev = g_hbuf[t & 1];
        float* __restrict__ hnew        = g_hbuf[(t + 1) & 1];
        const float* __restrict__ xp_t  = g_xproj + (size_t)t * BB * GG;
        float* __restrict__ hseq_t      = g_hseq + (size_t)t * BB * HH;

        float acc[4][4] = {};

        // prologue: chunk 0 -> buf0
#pragma unroll
        for (int r = 0; r < 4; r++) {
            int idx = tid + r * 256;
            int row = idx >> 4, c4 = idx & 15;
            cpasync16(sA0u + (row * APAD + c4 * 4) * 4,
                      hprev + (b0 + row) * HH + c4 * 4);
        }
        cpasync_commit();

#pragma unroll
        for (int ch = 0; ch < 8; ch++) {
            cpasync_waitall();
            __syncthreads();
            // prefetch next chunk (or xp tile into buf0 on the last chunk)
            uint32_t dstu = ((ch + 1) & 1) ? sA1u : sA0u;
            if (ch < 7) {
#pragma unroll
                for (int r = 0; r < 4; r++) {
                    int idx = tid + r * 256;
                    int row = idx >> 4, c4 = idx & 15;
                    cpasync16(dstu + (row * APAD + c4 * 4) * 4,
                              hprev + (b0 + row) * HH + (ch + 1) * 64 + c4 * 4);
                }
            } else {
#pragma unroll
                for (int r = 0; r < 4; r++) {
                    int idx = tid + r * 256;
                    int row = idx >> 4, c4 = idx & 15;
                    cpasync16(sA0u + (row * APAD + c4 * 4) * 4,
                              xp_t + (size_t)(b0 + row) * GG + n0 + c4 * 4);
                }
            }
            cpasync_commit();

            const float* sAc = (ch & 1) ? sA1 : sA0;
#pragma unroll
            for (int ks = 0; ks < 8; ks++) {
                int k0 = ks * 8;
                uint32_t a0 = __float_as_uint(sAc[(wm * 16 + gq    ) * APAD + k0 + q]);
                uint32_t a1 = __float_as_uint(sAc[(wm * 16 + gq + 8) * APAD + k0 + q]);
                uint32_t a2 = __float_as_uint(sAc[(wm * 16 + gq    ) * APAD + k0 + q + 4]);
                uint32_t a3 = __float_as_uint(sAc[(wm * 16 + gq + 8) * APAD + k0 + q + 4]);
                int kw = ch * 64 + k0;
#pragma unroll
                for (int nt = 0; nt < 4; nt++) {
                    int n = wn * 32 + nt * 8 + gq;
                    uint32_t b0f = __float_as_uint(sW[n * WPAD + kw + q]);
                    uint32_t b1f = __float_as_uint(sW[n * WPAD + kw + q + 4]);
                    mma_tf32(acc[nt][0], acc[nt][1], acc[nt][2], acc[nt][3],
                             a0, a1, a2, a3, b0f, b1f);
                }
            }
        }

        cpasync_waitall();    // xp tile landed in buf0
        __syncthreads();      // all warps done with buf1 (chunk 7)

        // stage gate tile into buf1 so each thread gets full (i,f,g,o) quadruples
        float* Gm = sA1;
#pragma unroll
        for (int nt = 0; nt < 4; nt++) {
            int col = wn * 32 + nt * 8 + q * 2;
            int row = wm * 16 + gq;
            Gm[row * 64 + col]           = acc[nt][0];
            Gm[row * 64 + col + 1]       = acc[nt][1];
            Gm[(row + 8) * 64 + col]     = acc[nt][2];
            Gm[(row + 8) * 64 + col + 1] = acc[nt][3];
        }
        __syncthreads();

#pragma unroll
        for (int s = 0; s < 4; s++) {
            int idx = tid + s * 256;
            int b = idx >> 4, j = idx & 15;
            float4 gm = *reinterpret_cast<float4*>(&Gm[b * 64 + j * 4]);
            float4 xp = *reinterpret_cast<float4*>(&sA0[b * APAD + j * 4]);
            float ig = sigmf(gm.x + xp.x);
            float fg = sigmf(gm.y + xp.y);
            float gg = tanhf(gm.z + xp.z);
            float og = sigmf(gm.w + xp.w);
            float c = fg * c_reg[s] + ig * gg;
            float h = tf32f(og * tanhf(c));      // pre-round: consumers all use tf32
            c_reg[s] = c;
            int ci = (b0 + b) * HH + j0 + j;
            hnew[ci] = h;
            if (LAYER == 0) hseq_t[ci] = h;
        }

        grid_sync();
    }
}

// ---------------- output head: relu(h_last) @ W_out^T + b_out ----------------
__global__ void final_kernel(const float* __restrict__ Wout, const float* __restrict__ bout,
                             float* __restrict__ out) {
    __shared__ float sw[HH];
    int tid = threadIdx.x;
    for (int i = tid; i < HH; i += 256) sw[i] = Wout[i];
    __syncthreads();
    const float* h = g_hbuf[0];  // T even -> last write landed in buffer 0
    float s = bout[0];
#pragma unroll 4
    for (int j = 0; j < HH; j++) {
        float v = h[tid * HH + j];
        v = v > 0.0f ? v : 0.0f;
        s += v * sw[j];
    }
    out[tid] = s;
}

// ---------------- launch ----------------
extern "C" void kernel_launch(void* const* d_in, const int* in_sizes, int n_in,
                              void* d_out, int out_size) {
    (void)in_sizes; (void)n_in; (void)out_size;
    const float* x    = (const float*)d_in[0];
    const float* Wih0 = (const float*)d_in[1];
    const float* Whh0 = (const float*)d_in[2];
    const float* bih0 = (const float*)d_in[3];
    const float* bhh0 = (const float*)d_in[4];
    const float* Wih1 = (const float*)d_in[5];
    const float* Whh1 = (const float*)d_in[6];
    const float* bih1 = (const float*)d_in[7];
    const float* bhh1 = (const float*)d_in[8];
    const float* Wout = (const float*)d_in[9];
    const float* bout = (const float*)d_in[10];
    float* out = (float*)d_out;

    cudaFuncSetAttribute(scan_kernel<0>, cudaFuncAttributeMaxDynamicSharedMemorySize, SMEM_SCAN);
    cudaFuncSetAttribute(scan_kernel<1>, cudaFuncAttributeMaxDynamicSharedMemorySize, SMEM_SCAN);

    prep_kernel<<<1024, 256>>>(Wih0, Whh0, bih0, bhh0, Wih1, Whh1, bih1, bhh1);

    dim3 gproj(2048, 32);   // (T*B)/64 x G/64

    inproj_kernel<IND, 0><<<gproj, 256>>>(x);
    scan_kernel<0><<<NCTA, 256, SMEM_SCAN>>>();

    inproj_kernel<HH, 1><<<gproj, 256>>>(nullptr);
    scan_kernel<1><<<NCTA, 256, SMEM_SCAN>>>();

    final_kernel<<<1, 256>>>(Wout, bout, out);
}